// round 14
// baseline (speedup 1.0000x reference)
#include <cuda_runtime.h>
#include <math.h>

// Problem constants (match reference)
#define FF       20
#define V_FIELD  5000
#define TOTALV   (FF * V_FIELD)     // 100000
#define DD       64
#define BB       8192
#define NPAIRS   190

#define WARPS_PER_BLOCK  2
#define NBLOCKS          (BB / WARPS_PER_BLOCK)  // 4096

// Converged structure: one warp per sample walks all 190 pairs; all 8192
// warps in one wave -> temporal L2 confinement keeps DRAM at the unique-row
// floor (~415MB) while L1<-L2 runs exactly at the chip LTS cap
// (797MB / 6300 B/cyc @ 1.76GHz = 71.9us = measured). R14 = R13 with the
// compile fix: make_meta() marked __host__ __device__ constexpr (the harness
// nvcc lacks --expt-relaxed-constexpr). Pair metadata is a compile-time
// constant table + FULL unroll, so i/j/bases are SASS immediates. No smem,
// no syncthreads, no meta loads, no loop overhead; per pair = 2 SHFL +
// 2 IADD + 2 LDG.64 + 2 FFMA.

struct MetaTable {
    int i[NPAIRS];
    int j[NPAIRS];
    int baseA[NPAIRS];   // float2-unit base of W[j, i*V_FIELD + *]
    int baseB[NPAIRS];   // float2-unit base of W[i, j*V_FIELD + *]
};

__host__ __device__ static constexpr MetaTable make_meta() {
    MetaTable t{};
    int p = 0;
    for (int i = 0; i < FF; i++)
        for (int j = i + 1; j < FF; j++) {
            t.i[p] = i;
            t.j[p] = j;
            t.baseA[p] = (j * TOTALV + i * V_FIELD) * (DD / 2);
            t.baseB[p] = (i * TOTALV + j * V_FIELD) * (DD / 2);
            p++;
        }
    return t;
}

__global__ void __launch_bounds__(WARPS_PER_BLOCK * 32)
ffm_all(const int* __restrict__ x, const float* __restrict__ W,
        const float* __restrict__ Wl, const float* __restrict__ bias,
        float* __restrict__ out) {
    static constexpr MetaTable M = make_meta();

    const int lane = threadIdx.x & 31;
    const int w    = threadIdx.x >> 5;
    const int s    = blockIdx.x * WARPS_PER_BLOCK + w;
    const float2* __restrict__ W2 = (const float2*)W;

    // Index row across lanes; lanes < FF seed the linear term, then the
    // index is pre-scaled to float2-row units (x32).
    int   xv  = 0;
    float acc = 0.f;
    if (lane < FF) {
        xv  = x[s * FF + lane];
        acc = __ldg(&Wl[lane * V_FIELD + xv]);
        xv *= (DD / 2);
    }

    #pragma unroll
    for (int q = 0; q < NPAIRS; q++) {
        // All of M.* are compile-time constants -> immediates after unroll.
        const int xi = __shfl_sync(0xffffffffu, xv, M.i[q]);
        const int xj = __shfl_sync(0xffffffffu, xv, M.j[q]);
        const float2 av = __ldg(W2 + (unsigned)(M.baseA[q] + xi) + lane);
        const float2 bv = __ldg(W2 + (unsigned)(M.baseB[q] + xj) + lane);
        acc = fmaf(av.x, bv.x, acc);
        acc = fmaf(av.y, bv.y, acc);
    }

    #pragma unroll
    for (int o = 16; o; o >>= 1)
        acc += __shfl_xor_sync(0xffffffffu, acc, o);
    if (lane == 0) {
        const float z = acc + bias[0];
        out[s] = 1.f / (1.f + __expf(-z));
    }
}

extern "C" void kernel_launch(void* const* d_in, const int* in_sizes, int n_in,
                              void* d_out, int out_size) {
    const int*   x    = (const int*)d_in[0];
    const float* W    = (const float*)d_in[1];
    const float* Wl   = (const float*)d_in[2];
    const float* bias = (const float*)d_in[3];
    float*       out  = (float*)d_out;

    ffm_all<<<NBLOCKS, WARPS_PER_BLOCK * 32>>>(x, W, Wl, bias, out);
}

// round 15
// speedup vs baseline: 1.4666x; 1.4666x over previous
#include <cuda_runtime.h>
#include <math.h>

// Problem constants (match reference)
#define FF       20
#define V_FIELD  5000
#define TOTALV   (FF * V_FIELD)     // 100000
#define DD       64
#define BB       8192
#define NPAIRS   190

#define WARPS_PER_BLOCK  2
#define NBLOCKS          (BB / WARPS_PER_BLOCK)  // 4096

// Converged structure: one warp per sample walks all 190 pairs; all 8192
// warps in one wave -> temporal L2 confinement keeps DRAM at the unique-row
// floor (~415MB) while L1<-L2 runs at the chip LTS cap (797MB / 6300 B/cyc
// = ~72us kernel time). R14 proved the loop must stay ROLLED (full unroll ->
// 25KB body -> I$ thrash, 97us). R15: keep the R12 rolled loop but source
// pair metadata from __constant__ memory (statically constexpr-initialized):
// no per-CTA meta build, no __syncthreads, no smem, LDC.128 uniform loads
// instead of LDS.128. Body otherwise byte-identical to R12 (70.5us).

struct MetaTable {
    int4 m[NPAIRS];   // {i, j, baseA, baseB}; bases in float2 units
};

__host__ __device__ static constexpr MetaTable make_meta() {
    MetaTable t{};
    int p = 0;
    for (int i = 0; i < FF; i++)
        for (int j = i + 1; j < FF; j++) {
            t.m[p].x = i;
            t.m[p].y = j;
            t.m[p].z = (j * TOTALV + i * V_FIELD) * (DD / 2);
            t.m[p].w = (i * TOTALV + j * V_FIELD) * (DD / 2);
            p++;
        }
    return t;
}

// Static (constexpr) initialization — no dynamic init, no runtime copy.
__constant__ MetaTable cM = make_meta();

__global__ void __launch_bounds__(WARPS_PER_BLOCK * 32)
ffm_all(const int* __restrict__ x, const float* __restrict__ W,
        const float* __restrict__ Wl, const float* __restrict__ bias,
        float* __restrict__ out) {
    const int lane = threadIdx.x & 31;
    const int w    = threadIdx.x >> 5;
    const int s    = blockIdx.x * WARPS_PER_BLOCK + w;
    const float2* __restrict__ W2 = (const float2*)W;

    // Index row across lanes; lanes < FF seed the linear term, then the
    // index is pre-scaled to float2-row units (x32).
    int   xv  = 0;
    float acc = 0.f;
    if (lane < FF) {
        xv  = x[s * FF + lane];
        acc = __ldg(&Wl[lane * V_FIELD + xv]);
        xv *= (DD / 2);
    }

    #pragma unroll 5
    for (int q = 0; q < NPAIRS; q++) {
        const int4 m = cM.m[q];   // LDC.128, uniform across warp
        const int xi = __shfl_sync(0xffffffffu, xv, m.x);
        const int xj = __shfl_sync(0xffffffffu, xv, m.y);
        const float2 av = __ldg(W2 + (unsigned)(m.z + xi) + lane);
        const float2 bv = __ldg(W2 + (unsigned)(m.w + xj) + lane);
        acc = fmaf(av.x, bv.x, acc);
        acc = fmaf(av.y, bv.y, acc);
    }

    #pragma unroll
    for (int o = 16; o; o >>= 1)
        acc += __shfl_xor_sync(0xffffffffu, acc, o);
    if (lane == 0) {
        const float z = acc + bias[0];
        out[s] = 1.f / (1.f + __expf(-z));
    }
}

extern "C" void kernel_launch(void* const* d_in, const int* in_sizes, int n_in,
                              void* d_out, int out_size) {
    const int*   x    = (const int*)d_in[0];
    const float* W    = (const float*)d_in[1];
    const float* Wl   = (const float*)d_in[2];
    const float* bias = (const float*)d_in[3];
    float*       out  = (float*)d_out;

    ffm_all<<<NBLOCKS, WARPS_PER_BLOCK * 32>>>(x, W, Wl, bias, out);
}